// round 14
// baseline (speedup 1.0000x reference)
#include <cuda_runtime.h>
#include <cuda_bf16.h>
#include <math.h>
#include <stdint.h>

#define BATCH  64
#define HD     128
#define OUTC   10

#define PITCHV 136      // V row pitch, bf16 elems
#define V0_OFF 0
#define V1_OFF (16 * PITCHV * 2)            // 4352
#define XS_OFF (2 * 16 * PITCHV * 2)        // 8704
#define LG_OFF (XS_OFF + 16 * 256 * 4)      // 25088
#define RI_OFF (LG_OFF + 64)
#define LT_OFF (RI_OFF + 64)
#define SMEM_MAIN (LT_OFF + 64)

// Chain matrices permuted into mma.m16n8k16 B-fragment order (bf16, 16.7 MB):
// uint4 index: m*4096 + c8*128 + kp*32 + lane,  c8 = n>>3  (0..31)
//   within uint4, u32 j: kc = 2*kp + (j>>1); reg = j&1
//   packed pair = M[k0][n], M[k0+1][n]; k0 = kc*16 + 2*(lane&3) + reg*8
//   n = c8*8 + (lane>>2);  M[k][2h+d] = cores[m][k][d][h]
__device__ uint32_t g_perm[(size_t)255 * 16384];

// ---------------- helpers ----------------
__device__ __forceinline__ uint32_t smem_u32(const void* p) {
    uint32_t a;
    asm("{ .reg .u64 t; cvta.to.shared.u64 t, %1; cvt.u32.u64 %0, t; }" : "=r"(a) : "l"(p));
    return a;
}
__device__ __forceinline__ void ldm_x4(uint32_t* r, uint32_t addr) {
    asm volatile("ldmatrix.sync.aligned.m8n8.x4.shared.b16 {%0,%1,%2,%3}, [%4];"
                 : "=r"(r[0]), "=r"(r[1]), "=r"(r[2]), "=r"(r[3]) : "r"(addr));
}
__device__ __forceinline__ void mma16816(float* c, const uint32_t* a,
                                         uint32_t b0, uint32_t b1) {
    asm volatile(
        "mma.sync.aligned.m16n8k16.row.col.f32.bf16.bf16.f32 "
        "{%0,%1,%2,%3}, {%4,%5,%6,%7}, {%8,%9}, {%0,%1,%2,%3};"
        : "+f"(c[0]), "+f"(c[1]), "+f"(c[2]), "+f"(c[3])
        : "r"(a[0]), "r"(a[1]), "r"(a[2]), "r"(a[3]), "r"(b0), "r"(b1));
}
__device__ __forceinline__ uint32_t packbf2(float a, float b) {
    __nv_bfloat162 t = __floats2bfloat162_rn(a, b);
    return *reinterpret_cast<uint32_t*>(&t);
}

// ---------------- pre-pass: coalesced SMEM-staged fragment permute ----------
__global__ void __launch_bounds__(256) conv_perm(const float* __restrict__ cores)
{
    __shared__ float ts[32][257];
    const int m = blockIdx.x, tid = threadIdx.x;
    const float* src = cores + (size_t)m * 32768;
    uint32_t* dst = g_perm + (size_t)m * 16384;

    for (int kp = 0; kp < 4; ++kp) {
        #pragma unroll
        for (int it = 0; it < 8; ++it) {
            int idx = it * 256 + tid;
            int k = idx >> 6, cg = (idx & 63) * 4;
            float4 v = *(const float4*)(src + (size_t)(kp * 32 + k) * 256 + cg);
            ts[k][cg + 0] = v.x; ts[k][cg + 1] = v.y;
            ts[k][cg + 2] = v.z; ts[k][cg + 3] = v.w;
        }
        __syncthreads();
        #pragma unroll
        for (int it = 0; it < 16; ++it) {
            int lin = it * 256 + tid;
            int j    = lin & 3;
            int lane = (lin >> 2) & 31;
            int c8   = lin >> 7;
            int k0l = 16 * (j >> 1) + 2 * (lane & 3) + ((j & 1) << 3);
            int n = c8 * 8 + (lane >> 2);
            int col = (n & 1) * 128 + (n >> 1);
            float lo = ts[k0l][col];
            float hi = ts[k0l + 1][col];
            dst[(size_t)c8 * 512 + kp * 128 + (lin & 127)] = packbf2(lo, hi);
        }
        __syncthreads();
    }
}

// ---------------- one chain step (16 warps, 2 n-tiles each) ----------------
__device__ __forceinline__ void chain_step(
    int m, bool prefetch, uint4* __restrict__ Bcur, uint4* __restrict__ Bnext,
    char* sm, uint32_t smb, uint32_t fragbase,
    int w, int l15, int lhi, int r, int q)
{
    float* XS   = (float*)(sm + XS_OFF);
    float* LOGS = (float*)(sm + LG_OFF);
    float* RINV = (float*)(sm + RI_OFF);

    // prefetch B(m+1): 8 coalesced LDG.128
    if (prefetch) {
        const uint4* bp = (const uint4*)g_perm + ((size_t)(m + 1) << 12) + fragbase;
        #pragma unroll
        for (int nt = 0; nt < 2; ++nt)
            #pragma unroll
            for (int kp = 0; kp < 4; ++kp)
                Bnext[nt * 4 + kp] = bp[nt * 128 + kp * 32];
    }

    const uint32_t vr = smb + ((m & 1) ? V1_OFF : V0_OFF);
    char* vw = sm + ((m & 1) ? V0_OFF : V1_OFF);

    __syncthreads();   // V(m) writes visible

    float acc[2][4];
    #pragma unroll
    for (int i = 0; i < 2; ++i)
        #pragma unroll
        for (int j = 0; j < 4; ++j) acc[i][j] = 0.f;

    // 2-deep rolling A pipeline
    uint32_t Aa[4], Ab[4];
    ldm_x4(Aa, vr + (uint32_t)(l15 * PITCHV + lhi) * 2);
    #pragma unroll
    for (int kc = 0; kc < 8; ++kc) {
        uint32_t* Ac = (kc & 1) ? Ab : Aa;
        uint32_t* An = (kc & 1) ? Aa : Ab;
        if (kc + 1 < 8)
            ldm_x4(An, vr + (uint32_t)(l15 * PITCHV + (kc + 1) * 16 + lhi) * 2);
        #pragma unroll
        for (int nt = 0; nt < 2; ++nt) {
            const uint4& v = Bcur[nt * 4 + (kc >> 1)];
            uint32_t b0 = (kc & 1) ? v.z : v.x;
            uint32_t b1 = (kc & 1) ? v.w : v.y;
            mma16816(acc[nt], Ac, b0, b1);
        }
    }

    // epilogue -> write buffer (ping-pong)
    const float xa = XS[r * 256 + m + 1];
    const float xb = XS[(r + 8) * 256 + m + 1];
    #pragma unroll
    for (int nt = 0; nt < 2; ++nt) {
        int h = w * 8 + nt * 4 + q;
        float v0 = fmaf(xa, acc[nt][1], (1.f - xa) * acc[nt][0]);
        float v1 = fmaf(xb, acc[nt][3], (1.f - xb) * acc[nt][2]);
        *(__nv_bfloat16*)(vw + r * (PITCHV * 2) + h * 2) = __float2bfloat16(v0);
        *(__nv_bfloat16*)(vw + (r + 8) * (PITCHV * 2) + h * 2) = __float2bfloat16(v1);
    }

    // periodic renormalization (512 threads: 16 rows x 32 segs x 4 elems)
    if (((m + 1) & 15) == 0 && m < 254) {
        const int tid = threadIdx.x;
        __syncthreads();
        int bb = tid >> 5, seg = tid & 31;
        __nv_bfloat16* vrow = (__nv_bfloat16*)(vw + bb * (PITCHV * 2));
        float s = 0.f;
        #pragma unroll
        for (int j = 0; j < 4; ++j) {
            float f = __bfloat162float(vrow[seg * 4 + j]);
            s = fmaf(f, f, s);
        }
        #pragma unroll
        for (int o = 16; o > 0; o >>= 1) s += __shfl_xor_sync(0xffffffffu, s, o);
        if (seg == 0) {
            float nrm = fmaxf(sqrtf(s), 1e-30f);
            LOGS[bb] += logf(nrm);
            RINV[bb] = 1.f / nrm;
        }
        __syncthreads();
        float ri = RINV[bb];
        #pragma unroll
        for (int j = 0; j < 4; ++j)
            vrow[seg * 4 + j] = __float2bfloat16(__bfloat162float(vrow[seg * 4 + j]) * ri);
        // visibility covered by next step's leading barrier
    }
}

// ---------------- main: batched vector chain, 512 threads ----------------
__global__ void __launch_bounds__(512, 1) mps_chain(
    const float* __restrict__ x, const float* __restrict__ core0,
    const float* __restrict__ classifier, float* __restrict__ out)
{
    __shared__ char sm[SMEM_MAIN];
    uint32_t smb = smem_u32(sm);
    const int tid = threadIdx.x, lane = tid & 31, w = tid >> 5;   // 16 warps
    const int b0 = blockIdx.x * 16;

    float* XS   = (float*)(sm + XS_OFF);
    float* LOGS = (float*)(sm + LG_OFF);
    float* RINV = (float*)(sm + RI_OFF);
    float* LTOT = (float*)(sm + LT_OFF);

    #pragma unroll
    for (int it = 0; it < 8; ++it) {
        int idx = it * 512 + tid;
        XS[idx] = x[(size_t)(b0 + (idx >> 8)) * 256 + (idx & 255)];
    }
    if (tid < 16) LOGS[tid] = 0.f;
    __syncthreads();

    // init V0[bb][h]
    #pragma unroll
    for (int it = 0; it < 4; ++it) {
        int idx = it * 512 + tid;
        int bb = idx >> 7, h = idx & 127;
        float xv = XS[bb * 256];
        float v = (1.f - xv) * core0[h] + xv * core0[HD + h];
        *(__nv_bfloat16*)(sm + V0_OFF + bb * (PITCHV * 2) + h * 2) = __float2bfloat16(v);
    }
    // step 0's leading barrier covers visibility

    const int l15 = lane & 15, lhi = (lane >> 4) << 3;
    const int r = lane >> 2, q = lane & 3;
    const uint32_t fragbase = (uint32_t)(2 * w) * 128 + lane;   // uint4 units

    // preload B(0)
    uint4 B0[8], B1[8];
    {
        const uint4* bp = (const uint4*)g_perm + fragbase;
        #pragma unroll
        for (int nt = 0; nt < 2; ++nt)
            #pragma unroll
            for (int kp = 0; kp < 4; ++kp)
                B0[nt * 4 + kp] = bp[nt * 128 + kp * 32];
    }

    for (int mm = 0; mm < 127; ++mm) {
        chain_step(2 * mm,     true, B0, B1, sm, smb, fragbase, w, l15, lhi, r, q);
        chain_step(2 * mm + 1, true, B1, B0, sm, smb, fragbase, w, l15, lhi, r, q);
    }
    chain_step(254, false, B0, B1, sm, smb, fragbase, w, l15, lhi, r, q);
    __syncthreads();

    // final norm + total log (V in V1)
    {
        int bb = tid >> 5, seg = tid & 31;
        const __nv_bfloat16* vrow = (const __nv_bfloat16*)(sm + V1_OFF + bb * (PITCHV * 2));
        float s = 0.f;
        #pragma unroll
        for (int j = 0; j < 4; ++j) {
            float f = __bfloat162float(vrow[seg * 4 + j]);
            s = fmaf(f, f, s);
        }
        #pragma unroll
        for (int o = 16; o > 0; o >>= 1) s += __shfl_xor_sync(0xffffffffu, s, o);
        if (seg == 0) {
            float nrm = fmaxf(sqrtf(s), 1e-30f);
            RINV[bb] = 1.f / nrm;
            LTOT[bb] = LOGS[bb] + logf(nrm);
        }
    }
    __syncthreads();

    if (tid < 16 * OUTC) {
        int bb = tid / OUTC, o = tid % OUTC;
        const __nv_bfloat16* vrow = (const __nv_bfloat16*)(sm + V1_OFF + bb * (PITCHV * 2));
        float s = 0.f;
        #pragma unroll
        for (int h = 0; h < HD; ++h)
            s = fmaf(__bfloat162float(vrow[h]), classifier[o * HD + h], s);
        out[(size_t)(b0 + bb) * OUTC + o] = s * RINV[bb] + LTOT[bb];
    }
}

extern "C" void kernel_launch(void* const* d_in, const int* in_sizes, int n_in,
                              void* d_out, int out_size)
{
    (void)in_sizes; (void)n_in; (void)out_size;
    const float* x          = (const float*)d_in[0];
    const float* core0      = (const float*)d_in[1];
    const float* cores      = (const float*)d_in[2];
    const float* classifier = (const float*)d_in[3];
    float*       out        = (float*)d_out;

    conv_perm<<<255, 256>>>(cores);
    mps_chain<<<4, 512>>>(x, core0, classifier, out);
}

// round 15
// speedup vs baseline: 1.2392x; 1.2392x over previous
#include <cuda_runtime.h>
#include <cuda_fp16.h>
#include <math.h>
#include <stdint.h>

#define BATCH  64
#define HD     128
#define OUTC   10

#define PITCHV 136      // V row pitch, fp16 elems
#define V0_OFF 0
#define V1_OFF (16 * PITCHV * 2)            // 4352
#define XS_OFF (2 * 16 * PITCHV * 2)        // 8704
#define LG_OFF (XS_OFF + 16 * 256 * 4)      // 25088
#define RI_OFF (LG_OFF + 64)
#define LT_OFF (RI_OFF + 64)
#define SMEM_MAIN (LT_OFF + 64)

// ln(8) * 255 — exact correction for the per-step x8 scale
#define LOG_CORR (255.0f * 2.07944154f)

// Chain matrices permuted into mma.m16n8k16 B-fragment order (fp16, 16.7 MB):
// uint4 index: m*4096 + c8*128 + kp*32 + lane,  c8 = n>>3  (0..31)
//   within uint4, u32 j: kc = 2*kp + (j>>1); reg = j&1
//   packed pair = M[k0][n], M[k0+1][n]; k0 = kc*16 + 2*(lane&3) + reg*8
//   n = c8*8 + (lane>>2);  M[k][2h+d] = cores[m][k][d][h]
__device__ uint32_t g_perm[(size_t)255 * 16384];

// ---------------- helpers ----------------
__device__ __forceinline__ uint32_t smem_u32(const void* p) {
    uint32_t a;
    asm("{ .reg .u64 t; cvta.to.shared.u64 t, %1; cvt.u32.u64 %0, t; }" : "=r"(a) : "l"(p));
    return a;
}
__device__ __forceinline__ void ldm_x4(uint32_t* r, uint32_t addr) {
    asm volatile("ldmatrix.sync.aligned.m8n8.x4.shared.b16 {%0,%1,%2,%3}, [%4];"
                 : "=r"(r[0]), "=r"(r[1]), "=r"(r[2]), "=r"(r[3]) : "r"(addr));
}
// f16-accumulate HMMA: D,C are 2x f16x2 regs
__device__ __forceinline__ void mma16816h(uint32_t* c, const uint32_t* a,
                                          uint32_t b0, uint32_t b1) {
    asm volatile(
        "mma.sync.aligned.m16n8k16.row.col.f16.f16.f16.f16 "
        "{%0,%1}, {%2,%3,%4,%5}, {%6,%7}, {%0,%1};"
        : "+r"(c[0]), "+r"(c[1])
        : "r"(a[0]), "r"(a[1]), "r"(a[2]), "r"(a[3]), "r"(b0), "r"(b1));
}
__device__ __forceinline__ uint32_t packh2(float a, float b) {
    __half2 t = __floats2half2_rn(a, b);
    return *reinterpret_cast<uint32_t*>(&t);
}

// ---------------- pre-pass: coalesced SMEM-staged fragment permute ----------
__global__ void __launch_bounds__(256) conv_perm(const float* __restrict__ cores)
{
    __shared__ float ts[32][257];
    const int m = blockIdx.x, tid = threadIdx.x;
    const float* src = cores + (size_t)m * 32768;
    uint32_t* dst = g_perm + (size_t)m * 16384;

    for (int kp = 0; kp < 4; ++kp) {
        #pragma unroll
        for (int it = 0; it < 8; ++it) {
            int idx = it * 256 + tid;
            int k = idx >> 6, cg = (idx & 63) * 4;
            float4 v = *(const float4*)(src + (size_t)(kp * 32 + k) * 256 + cg);
            ts[k][cg + 0] = v.x; ts[k][cg + 1] = v.y;
            ts[k][cg + 2] = v.z; ts[k][cg + 3] = v.w;
        }
        __syncthreads();
        #pragma unroll
        for (int it = 0; it < 16; ++it) {
            int lin = it * 256 + tid;
            int j    = lin & 3;
            int lane = (lin >> 2) & 31;
            int c8   = lin >> 7;
            int k0l = 16 * (j >> 1) + 2 * (lane & 3) + ((j & 1) << 3);
            int n = c8 * 8 + (lane >> 2);
            int col = (n & 1) * 128 + (n >> 1);
            float lo = ts[k0l][col];
            float hi = ts[k0l + 1][col];
            dst[(size_t)c8 * 512 + kp * 128 + (lin & 127)] = packh2(lo, hi);
        }
        __syncthreads();
    }
}

// ---------------- one chain step ----------------
__device__ __forceinline__ void chain_step(
    int m, bool prefetch, uint4* __restrict__ Bcur, uint4* __restrict__ Bnext,
    char* sm, uint32_t smb, uint32_t fragbase,
    int lane, int wc, int l15, int lhi, int r, int q)
{
    float* XS   = (float*)(sm + XS_OFF);
    float* LOGS = (float*)(sm + LG_OFF);
    float* RINV = (float*)(sm + RI_OFF);

    // prefetch B(m+1): 16 coalesced LDG.128
    if (prefetch) {
        const uint4* bp = (const uint4*)g_perm + ((size_t)(m + 1) << 12) + fragbase;
        #pragma unroll
        for (int i = 0; i < 16; ++i)
            Bnext[i] = bp[i * 32];
    }

    const uint32_t vr = smb + ((m & 1) ? V1_OFF : V0_OFF);
    char* vw = sm + ((m & 1) ? V0_OFF : V1_OFF);

    __syncthreads();   // V(m) writes visible

    uint32_t acc[4][2];
    #pragma unroll
    for (int i = 0; i < 4; ++i) { acc[i][0] = 0u; acc[i][1] = 0u; }

    // interleaved A-ldmatrix / MMA
    uint32_t A[8][4];
    ldm_x4(A[0], vr + (uint32_t)(l15 * PITCHV + 0 * 16 + lhi) * 2);
    ldm_x4(A[1], vr + (uint32_t)(l15 * PITCHV + 1 * 16 + lhi) * 2);
    #pragma unroll
    for (int kc = 0; kc < 8; ++kc) {
        if (kc + 2 < 8)
            ldm_x4(A[kc + 2], vr + (uint32_t)(l15 * PITCHV + (kc + 2) * 16 + lhi) * 2);
        #pragma unroll
        for (int nt = 0; nt < 4; ++nt) {
            const uint4& v = Bcur[nt * 4 + (kc >> 1)];
            uint32_t b0 = (kc & 1) ? v.z : v.x;
            uint32_t b1 = (kc & 1) ? v.w : v.y;
            mma16816h(acc[nt], A[kc], b0, b1);
        }
    }

    // epilogue: acc[nt][0] = row r (U,W) packed; acc[nt][1] = row r+8.
    // V_new = 8 * ((1-x)*U + x*W)   (x8 scale corrected in final log)
    const float xa = XS[r * 256 + m + 1];
    const float xb = XS[(r + 8) * 256 + m + 1];
    #pragma unroll
    for (int nt = 0; nt < 4; ++nt) {
        int h = wc * 16 + nt * 4 + q;
        float2 f0 = __half22float2(*(const __half2*)&acc[nt][0]);
        float2 f1 = __half22float2(*(const __half2*)&acc[nt][1]);
        float v0 = 8.f * fmaf(xa, f0.y, (1.f - xa) * f0.x);
        float v1 = 8.f * fmaf(xb, f1.y, (1.f - xb) * f1.x);
        *(__half*)(vw + r * (PITCHV * 2) + h * 2) = __float2half_rn(v0);
        *(__half*)(vw + (r + 8) * (PITCHV * 2) + h * 2) = __float2half_rn(v1);
    }

    // renormalize every 8 steps (fp16 range management)
    if (((m + 1) & 7) == 0 && m < 254) {
        const int tid = threadIdx.x;
        __syncthreads();
        int bb = tid >> 4, seg = tid & 15;
        __half* vrow = (__half*)(vw + bb * (PITCHV * 2));
        float s = 0.f;
        #pragma unroll
        for (int j = 0; j < 8; ++j) {
            float f = __half2float(vrow[seg * 8 + j]);
            s = fmaf(f, f, s);
        }
        #pragma unroll
        for (int o = 8; o > 0; o >>= 1) s += __shfl_xor_sync(0xffffffffu, s, o);
        if (seg == 0) {
            float nrm = fmaxf(sqrtf(s), 1e-30f);
            LOGS[bb] += logf(nrm);
            RINV[bb] = 1.f / nrm;
        }
        __syncthreads();
        float ri = RINV[bb];
        #pragma unroll
        for (int j = 0; j < 8; ++j)
            vrow[seg * 8 + j] = __float2half_rn(__half2float(vrow[seg * 8 + j]) * ri);
        // visibility covered by next step's leading barrier
    }
}

// ---------------- main: batched vector chain ----------------
__global__ void __launch_bounds__(256, 1) mps_chain(
    const float* __restrict__ x, const float* __restrict__ core0,
    const float* __restrict__ classifier, float* __restrict__ out)
{
    __shared__ char sm[SMEM_MAIN];
    uint32_t smb = smem_u32(sm);
    const int tid = threadIdx.x, lane = tid & 31, wc = tid >> 5;
    const int b0 = blockIdx.x * 16;

    float* XS   = (float*)(sm + XS_OFF);
    float* LOGS = (float*)(sm + LG_OFF);
    float* RINV = (float*)(sm + RI_OFF);
    float* LTOT = (float*)(sm + LT_OFF);

    #pragma unroll
    for (int it = 0; it < 16; ++it) {
        int idx = it * 256 + tid;
        XS[idx] = x[(size_t)(b0 + (idx >> 8)) * 256 + (idx & 255)];
    }
    if (tid < 16) LOGS[tid] = 0.f;
    __syncthreads();

    // init V0[bb][h]
    #pragma unroll
    for (int it = 0; it < 8; ++it) {
        int idx = it * 256 + tid;
        int bb = idx >> 7, h = idx & 127;
        float xv = XS[bb * 256];
        float v = (1.f - xv) * core0[h] + xv * core0[HD + h];
        *(__half*)(sm + V0_OFF + bb * (PITCHV * 2) + h * 2) = __float2half_rn(v);
    }
    // step 0's leading barrier covers visibility

    const int l15 = lane & 15, lhi = (lane >> 4) << 3;
    const int r = lane >> 2, q = lane & 3;
    const uint32_t fragbase = (uint32_t)(wc * 16) * 32 + lane;

    // preload B(0)
    uint4 B0[16], B1[16];
    {
        const uint4* bp = (const uint4*)g_perm + fragbase;
        #pragma unroll
        for (int i = 0; i < 16; ++i) B0[i] = bp[i * 32];
    }

    for (int mm = 0; mm < 127; ++mm) {
        chain_step(2 * mm,     true, B0, B1, sm, smb, fragbase, lane, wc, l15, lhi, r, q);
        chain_step(2 * mm + 1, true, B1, B0, sm, smb, fragbase, lane, wc, l15, lhi, r, q);
    }
    chain_step(254, false, B0, B1, sm, smb, fragbase, lane, wc, l15, lhi, r, q);
    __syncthreads();

    // final norm + total log (V in V1); subtract exact x8-per-step correction
    {
        int bb = tid >> 4, seg = tid & 15;
        const __half* vrow = (const __half*)(sm + V1_OFF + bb * (PITCHV * 2));
        float s = 0.f;
        #pragma unroll
        for (int j = 0; j < 8; ++j) {
            float f = __half2float(vrow[seg * 8 + j]);
            s = fmaf(f, f, s);
        }
        #pragma unroll
        for (int o = 8; o > 0; o >>= 1) s += __shfl_xor_sync(0xffffffffu, s, o);
        if (seg == 0) {
            float nrm = fmaxf(sqrtf(s), 1e-30f);
            RINV[bb] = 1.f / nrm;
            LTOT[bb] = LOGS[bb] + logf(nrm) - LOG_CORR;
        }
    }
    __syncthreads();

    if (tid < 16 * OUTC) {
        int bb = tid / OUTC, o = tid % OUTC;
        const __half* vrow = (const __half*)(sm + V1_OFF + bb * (PITCHV * 2));
        float s = 0.f;
        #pragma unroll
        for (int h = 0; h < HD; ++h)
            s = fmaf(__half2float(vrow[h]), classifier[o * HD + h], s);
        out[(size_t)(b0 + bb) * OUTC + o] = s * RINV[bb] + LTOT[bb];
    }
}

extern "C" void kernel_launch(void* const* d_in, const int* in_sizes, int n_in,
                              void* d_out, int out_size)
{
    (void)in_sizes; (void)n_in; (void)out_size;
    const float* x          = (const float*)d_in[0];
    const float* core0      = (const float*)d_in[1];
    const float* cores      = (const float*)d_in[2];
    const float* classifier = (const float*)d_in[3];
    float*       out        = (float*)d_out;

    conv_perm<<<255, 256>>>(cores);
    mps_chain<<<4, 256>>>(x, core0, classifier, out);
}